// round 3
// baseline (speedup 1.0000x reference)
#include <cuda_runtime.h>
#include <cstdint>

#define NP 200000
#define NO 100000
#define NL 50000
#define NE 1000000
#define HD 64

// ---------------- device scratch (static, allowed) ----------------
__device__ float g_nodes[2][(size_t)(NP + NO + NL) * HD];                 // double-buffered features
__device__ float g_agg[(size_t)(3 * NP + NO + NL) * HD];                  // per-relation aggregates
__device__ int   g_cnt[3 * NP + NO + NL];                                 // in-degree counts
__device__ float g_sums[3 * HD];                                          // column sums for global mean

// ---------------- utility kernels ----------------
__global__ void zero_kernel(float* __restrict__ p, size_t n) {
    size_t n4 = n >> 2;
    float4 z = make_float4(0.f, 0.f, 0.f, 0.f);
    for (size_t i = (size_t)blockIdx.x * blockDim.x + threadIdx.x; i < n4;
         i += (size_t)gridDim.x * blockDim.x)
        reinterpret_cast<float4*>(p)[i] = z;
}

__global__ void gather_kernel(const int* __restrict__ idx, const float* __restrict__ emb,
                              float* __restrict__ out, int n) {
    int total = n * 16;  // 16 float4 per node (H=64)
    for (int i = blockIdx.x * blockDim.x + threadIdx.x; i < total;
         i += gridDim.x * blockDim.x) {
        int node = i >> 4, c = i & 15;
        int e = __ldg(&idx[node]);
        reinterpret_cast<float4*>(out)[(size_t)node * 16 + c] =
            reinterpret_cast<const float4*>(emb)[(size_t)e * 16 + c];
    }
}

__global__ void count_kernel(const int* __restrict__ dst, int* __restrict__ cnt, int E) {
    for (int i = blockIdx.x * blockDim.x + threadIdx.x; i < E;
         i += gridDim.x * blockDim.x)
        atomicAdd(&cnt[dst[i]], 1);
}

// ---------------- edge scatter: agg[dst] += x[src] ----------------
__global__ void scatter_kernel(const float* __restrict__ xsrc, const int* __restrict__ src,
                               const int* __restrict__ dst, float* __restrict__ agg, int E) {
    const int lane = threadIdx.x & 31;
    const int warp = (blockIdx.x * blockDim.x + threadIdx.x) >> 5;
    const int nwarps = (gridDim.x * blockDim.x) >> 5;
    for (int base = warp * 32; base < E; base += nwarps * 32) {
        int e = base + lane;
        int s = 0, d = 0;
        if (e < E) { s = src[e]; d = dst[e]; }
        int m = min(32, E - base);
#pragma unroll 4
        for (int j = 0; j < m; j++) {
            int sj = __shfl_sync(0xffffffffu, s, j);
            int dj = __shfl_sync(0xffffffffu, d, j);
            float2 v = *reinterpret_cast<const float2*>(xsrc + (size_t)sj * HD + 2 * lane);
            float* a = agg + (size_t)dj * HD + 2 * lane;
            asm volatile("red.global.add.v2.f32 [%0], {%1, %2};"
                         :: "l"(a), "f"(v.x), "f"(v.y) : "memory");
        }
    }
}

// ---------------- fused SAGE combine: out = relu((sum_r mean_r@Wl_r^T + b_r + x@Wr_r^T)/NR) + x
template <int NR>
__global__ void __launch_bounds__(256) combine_kernel(
    const float* __restrict__ x, float* __restrict__ out, int n,
    const float* __restrict__ agg0, const int* __restrict__ cnt0,
    const float* __restrict__ agg1, const int* __restrict__ cnt1,
    const float* __restrict__ agg2, const int* __restrict__ cnt2,
    const float* __restrict__ Wl, const float* __restrict__ blv,
    const float* __restrict__ Wr, int t, int r0, int r1, int r2) {
    extern __shared__ float sm[];
    float* WT    = sm;                   // NR * 4096, transposed lin_l weights
    float* WrT   = WT + NR * 4096;       // 4096, transposed SUM of root weights
    float* bias  = WrT + 4096;           // 64, summed biases
    float* stage = bias + 64;            // 8 warps * (NR+1)*64 staging

    const int rs[3] = {r0, r1, r2};
    const int tid = threadIdx.x;
    for (int r = 0; r < NR; r++) {
        const float* W = Wl + ((size_t)t * 5 + rs[r]) * 4096;
        for (int i = tid; i < 4096; i += 256) {
            int c = i >> 6, k = i & 63;
            WT[r * 4096 + k * 64 + c] = W[i];
        }
    }
    for (int i = tid; i < 4096; i += 256) {
        int c = i >> 6, k = i & 63;
        float s = 0.f;
#pragma unroll
        for (int r = 0; r < NR; r++) s += Wr[((size_t)t * 5 + rs[r]) * 4096 + i];
        WrT[k * 64 + c] = s;
    }
    if (tid < 64) {
        float s = 0.f;
#pragma unroll
        for (int r = 0; r < NR; r++) s += blv[((size_t)t * 5 + rs[r]) * 64 + tid];
        bias[tid] = s;
    }
    __syncthreads();

    const int lane = tid & 31, w = tid >> 5;
    const int wg = blockIdx.x * 8 + w;
    const int nw = gridDim.x * 8;
    float* st = stage + w * (NR + 1) * 64;
    const float* aggs[3] = {agg0, agg1, agg2};
    const int* cnts[3] = {cnt0, cnt1, cnt2};
    const float inv = 1.0f / (float)NR;

    for (int nd = wg; nd < n; nd += nw) {
#pragma unroll
        for (int r = 0; r < NR; r++) {
            float ic = 1.0f / (float)max(cnts[r][nd], 1);
            float2 v = *reinterpret_cast<const float2*>(aggs[r] + (size_t)nd * HD + 2 * lane);
            st[r * 64 + 2 * lane]     = v.x * ic;
            st[r * 64 + 2 * lane + 1] = v.y * ic;
        }
        float2 xv = *reinterpret_cast<const float2*>(x + (size_t)nd * HD + 2 * lane);
        st[NR * 64 + 2 * lane]     = xv.x;
        st[NR * 64 + 2 * lane + 1] = xv.y;
        __syncwarp();

        float2 acc = *reinterpret_cast<const float2*>(bias + 2 * lane);
#pragma unroll 8
        for (int k = 0; k < 64; k++) {
            float xk = st[NR * 64 + k];
            float2 wv = *reinterpret_cast<const float2*>(WrT + k * 64 + 2 * lane);
            acc.x = fmaf(xk, wv.x, acc.x);
            acc.y = fmaf(xk, wv.y, acc.y);
#pragma unroll
            for (int r = 0; r < NR; r++) {
                float mk = st[r * 64 + k];
                float2 wl = *reinterpret_cast<const float2*>(WT + r * 4096 + k * 64 + 2 * lane);
                acc.x = fmaf(mk, wl.x, acc.x);
                acc.y = fmaf(mk, wl.y, acc.y);
            }
        }
        float2 res;
        res.x = fmaxf(acc.x * inv, 0.f) + xv.x;
        res.y = fmaxf(acc.y * inv, 0.f) + xv.y;
        *reinterpret_cast<float2*>(out + (size_t)nd * HD + 2 * lane) = res;
        __syncwarp();
    }
}

// ---------------- column sums for global mean pooling ----------------
__global__ void colsum_kernel(const float* __restrict__ x, int n, float* __restrict__ outsum) {
    const int lane = threadIdx.x & 31;
    const int w = (blockIdx.x * blockDim.x + threadIdx.x) >> 5;
    const int nw = (gridDim.x * blockDim.x) >> 5;
    float2 acc = make_float2(0.f, 0.f);
    for (int r = w; r < n; r += nw) {
        float2 v = *reinterpret_cast<const float2*>(x + (size_t)r * HD + 2 * lane);
        acc.x += v.x; acc.y += v.y;
    }
    float* a = outsum + 2 * lane;
    asm volatile("red.global.add.v2.f32 [%0], {%1, %2};"
                 :: "l"(a), "f"(acc.x), "f"(acc.y) : "memory");
}

// ---------------- crime head (tiny) ----------------
__global__ void head_kernel(const float* __restrict__ gsum,
                            const float* __restrict__ Wc1, const float* __restrict__ bc1,
                            const float* __restrict__ Wc2, const float* __restrict__ bc2,
                            float* __restrict__ out) {
    __shared__ float g[192];
    __shared__ float h[64];
    int tid = threadIdx.x;
    if (tid < 192) {
        float nrm = tid < 64 ? (1.f / NP) : (tid < 128 ? (1.f / NO) : (1.f / NL));
        g[tid] = gsum[tid] * nrm;
    }
    __syncthreads();
    if (tid < 64) {
        float a = bc1[tid];
        for (int k = 0; k < 192; k++) a = fmaf(g[k], Wc1[tid * 192 + k], a);
        h[tid] = fmaxf(a, 0.f);
    }
    __syncthreads();
    if (tid < 20) {
        float a = bc2[tid];
        for (int k = 0; k < 64; k++) a = fmaf(h[k], Wc2[tid * 64 + k], a);
        out[tid] = a;
    }
}

// ---------------- suspect head: per-person MLP 64->32->1 ----------------
__global__ void __launch_bounds__(256) suspect_kernel(
    const float* __restrict__ p, const float* __restrict__ Ws1, const float* __restrict__ bs1,
    const float* __restrict__ Ws2, const float* __restrict__ bs2, float* __restrict__ out) {
    __shared__ float W1T[64 * 32];  // W1T[k][j] = Ws1[j*64+k]
    __shared__ float w2[32], b1[32];
    __shared__ float stage[8][64];
    int tid = threadIdx.x;
    for (int i = tid; i < 2048; i += 256) {
        int j = i >> 6, k = i & 63;
        W1T[k * 32 + j] = Ws1[i];
    }
    if (tid < 32) { w2[tid] = Ws2[tid]; b1[tid] = bs1[tid]; }
    __syncthreads();
    const float b2 = __ldg(bs2);
    const int lane = tid & 31, w = tid >> 5;
    const int wg = blockIdx.x * 8 + w;
    const int nw = gridDim.x * 8;
    for (int nd = wg; nd < NP; nd += nw) {
        float2 v = *reinterpret_cast<const float2*>(p + (size_t)nd * HD + 2 * lane);
        stage[w][2 * lane] = v.x; stage[w][2 * lane + 1] = v.y;
        __syncwarp();
        float acc = b1[lane];
#pragma unroll 8
        for (int k = 0; k < 64; k++)
            acc = fmaf(stage[w][k], W1T[k * 32 + lane], acc);
        float s = fmaxf(acc, 0.f) * w2[lane];
#pragma unroll
        for (int off = 16; off; off >>= 1) s += __shfl_xor_sync(0xffffffffu, s, off);
        if (lane == 0) out[20 + nd] = s + b2;
        __syncwarp();
    }
}

// ---------------- orchestration ----------------
extern "C" void kernel_launch(void* const* d_in, const int* in_sizes, int n_in,
                              void* d_out, int out_size) {
    const int* x_person   = (const int*)d_in[0];
    const int* x_object   = (const int*)d_in[1];
    const int* x_location = (const int*)d_in[2];
    const int* acts_src = (const int*)d_in[3];
    const int* acts_dst = (const int*)d_in[4];
    const int* uses_src = (const int*)d_in[5];
    const int* uses_dst = (const int*)d_in[6];
    const int* at_src   = (const int*)d_in[7];
    const int* at_dst   = (const int*)d_in[8];
    const float* person_emb   = (const float*)d_in[9];
    const float* object_emb   = (const float*)d_in[10];
    const float* location_emb = (const float*)d_in[11];
    const float* Wl  = (const float*)d_in[12];
    const float* bl  = (const float*)d_in[13];
    const float* Wr  = (const float*)d_in[14];
    const float* Wc1 = (const float*)d_in[15];
    const float* bc1 = (const float*)d_in[16];
    const float* Wc2 = (const float*)d_in[17];
    const float* bc2 = (const float*)d_in[18];
    const float* Ws1 = (const float*)d_in[19];
    const float* bs1 = (const float*)d_in[20];
    const float* Ws2 = (const float*)d_in[21];
    const float* bs2 = (const float*)d_in[22];
    float* out = (float*)d_out;

    float* nodes = nullptr; cudaGetSymbolAddress((void**)&nodes, g_nodes);
    float* agg   = nullptr; cudaGetSymbolAddress((void**)&agg, g_agg);
    int*   cnt   = nullptr; cudaGetSymbolAddress((void**)&cnt, g_cnt);
    float* sums  = nullptr; cudaGetSymbolAddress((void**)&sums, g_sums);

    const size_t NODESZ = (size_t)(NP + NO + NL) * HD;
    float* bufA = nodes;
    float* bufB = nodes + NODESZ;

    float* aggp1 = agg;
    float* aggp2 = agg + (size_t)NP * HD;
    float* aggp3 = agg + (size_t)2 * NP * HD;
    float* aggo  = agg + (size_t)3 * NP * HD;
    float* aggl  = agg + ((size_t)3 * NP + NO) * HD;
    int* cntp1 = cnt;
    int* cntp2 = cnt + NP;
    int* cntp3 = cnt + 2 * NP;
    int* cnto  = cnt + 3 * NP;
    int* cntl  = cnt + 3 * NP + NO;

    const int SM3 = (3 + 1) * 4096 * 4 + 64 * 4 + 8 * 4 * 64 * 4;  // 73984 B
    const int SM1 = (1 + 1) * 4096 * 4 + 64 * 4 + 8 * 2 * 64 * 4;  // 37120 B
    cudaFuncSetAttribute(combine_kernel<3>, cudaFuncAttributeMaxDynamicSharedMemorySize, SM3);

    // Phase A: embedding gathers
    gather_kernel<<<2048, 256>>>(x_person, person_emb, bufA, NP);
    gather_kernel<<<1024, 256>>>(x_object, object_emb, bufA + (size_t)NP * HD, NO);
    gather_kernel<<<512, 256>>>(x_location, location_emb, bufA + (size_t)(NP + NO) * HD, NL);

    // Phase B: in-degree counts (layer-invariant)
    zero_kernel<<<512, 256>>>((float*)cnt, (size_t)(3 * NP + NO + NL));
    count_kernel<<<1024, 256>>>(acts_dst, cntp1, NE);
    count_kernel<<<1024, 256>>>(uses_src, cntp2, NE);
    count_kernel<<<1024, 256>>>(at_src,   cntp3, NE);
    count_kernel<<<1024, 256>>>(uses_dst, cnto,  NE);
    count_kernel<<<1024, 256>>>(at_dst,   cntl,  NE);

    // Phase C: 3 GNN layers
    float* pc = bufA;
    float* pn = bufB;
    for (int t = 0; t < 3; t++) {
        zero_kernel<<<8192, 256>>>(agg, (size_t)(3 * NP + NO + NL) * HD);
        float* p = pc;
        float* o = pc + (size_t)NP * HD;
        float* l = pc + (size_t)(NP + NO) * HD;
        scatter_kernel<<<2048, 256>>>(p, acts_src, acts_dst, aggp1, NE);
        scatter_kernel<<<2048, 256>>>(o, uses_dst, uses_src, aggp2, NE);
        scatter_kernel<<<2048, 256>>>(l, at_dst,   at_src,   aggp3, NE);
        scatter_kernel<<<2048, 256>>>(p, uses_src, uses_dst, aggo,  NE);
        scatter_kernel<<<2048, 256>>>(p, at_src,   at_dst,   aggl,  NE);

        combine_kernel<3><<<444, 256, SM3>>>(p, pn, NP,
            aggp1, cntp1, aggp2, cntp2, aggp3, cntp3, Wl, bl, Wr, t, 0, 2, 4);
        combine_kernel<1><<<592, 256, SM1>>>(o, pn + (size_t)NP * HD, NO,
            aggo, cnto, nullptr, nullptr, nullptr, nullptr, Wl, bl, Wr, t, 1, 0, 0);
        combine_kernel<1><<<592, 256, SM1>>>(l, pn + (size_t)(NP + NO) * HD, NL,
            aggl, cntl, nullptr, nullptr, nullptr, nullptr, Wl, bl, Wr, t, 3, 0, 0);

        float* tmp = pc; pc = pn; pn = tmp;
    }

    // Phase D: heads
    float* p = pc;
    float* o = pc + (size_t)NP * HD;
    float* l = pc + (size_t)(NP + NO) * HD;
    zero_kernel<<<1, 64>>>(sums, 192);
    colsum_kernel<<<1024, 256>>>(p, NP, sums);
    colsum_kernel<<<512, 256>>>(o, NO, sums + 64);
    colsum_kernel<<<256, 256>>>(l, NL, sums + 128);
    head_kernel<<<1, 256>>>(sums, Wc1, bc1, Wc2, bc2, out);
    suspect_kernel<<<2048, 256>>>(p, Ws1, bs1, Ws2, bs2, out);
}

// round 5
// speedup vs baseline: 1.2669x; 1.2669x over previous
#include <cuda_runtime.h>
#include <cstdint>

#define NP 200000
#define NO 100000
#define NL 50000
#define NE 1000000
#define HD 64

// ---------------- device scratch (static, allowed) ----------------
__device__ float g_nodes[2][(size_t)(NP + NO + NL) * HD];   // double-buffered features
__device__ int   g_csr[5][NE];                              // CSR neighbor lists
__device__ int   g_rowoff[3 * (NP + 1) + (NO + 1) + (NL + 1)];
__device__ int   g_cnt[3 * NP + NO + NL];                   // counts / cursors
__device__ int   g_part[5 * 64];                            // scan partials
__device__ float g_sums[3 * HD];                            // column sums

// ---------------- utility kernels ----------------
__global__ void zero_kernel(float* __restrict__ p, size_t n) {
    size_t n4 = n >> 2;
    float4 z = make_float4(0.f, 0.f, 0.f, 0.f);
    for (size_t i = (size_t)blockIdx.x * blockDim.x + threadIdx.x; i < n4;
         i += (size_t)gridDim.x * blockDim.x)
        reinterpret_cast<float4*>(p)[i] = z;
}

__global__ void gather_kernel(const int* __restrict__ idx, const float* __restrict__ emb,
                              float* __restrict__ out, int n) {
    int total = n * 16;
    for (int i = blockIdx.x * blockDim.x + threadIdx.x; i < total;
         i += gridDim.x * blockDim.x) {
        int node = i >> 4, c = i & 15;
        int e = __ldg(&idx[node]);
        reinterpret_cast<float4*>(out)[(size_t)node * 16 + c] =
            reinterpret_cast<const float4*>(emb)[(size_t)e * 16 + c];
    }
}

__global__ void count_kernel(const int* __restrict__ dst, int* __restrict__ cnt, int E) {
    for (int i = blockIdx.x * blockDim.x + threadIdx.x; i < E;
         i += gridDim.x * blockDim.x)
        atomicAdd(&cnt[dst[i]], 1);
}

// ---------------- 3-phase exclusive scan ----------------
#define SCHUNK 4096
__global__ void scan_reduce(const int* __restrict__ in, int* __restrict__ part, int n) {
    __shared__ int s[256];
    int base = blockIdx.x * SCHUNK;
    int acc = 0;
    for (int i = threadIdx.x; i < SCHUNK; i += 256) {
        int idx = base + i;
        if (idx < n) acc += in[idx];
    }
    s[threadIdx.x] = acc;
    __syncthreads();
    for (int off = 128; off; off >>= 1) {
        if (threadIdx.x < off) s[threadIdx.x] += s[threadIdx.x + off];
        __syncthreads();
    }
    if (threadIdx.x == 0) part[blockIdx.x] = s[0];
}

__global__ void scan_part(int* part, int nb) {
    if (threadIdx.x == 0) {
        int run = 0;
        for (int i = 0; i < nb; i++) { int v = part[i]; part[i] = run; run += v; }
        part[nb] = run;
    }
}

__global__ void scan_write(const int* __restrict__ in, const int* __restrict__ part,
                           int* __restrict__ ro, int n, int nb) {
    __shared__ int wsum[8];
    int base = blockIdx.x * SCHUNK;
    int vals[16];
    int tsum = 0;
    int tb = base + threadIdx.x * 16;
#pragma unroll
    for (int j = 0; j < 16; j++) {
        int idx = tb + j;
        int v = (idx < n) ? in[idx] : 0;
        vals[j] = tsum;
        tsum += v;
    }
    int lane = threadIdx.x & 31, wp = threadIdx.x >> 5;
    int xs = tsum;
#pragma unroll
    for (int off = 1; off < 32; off <<= 1) {
        int y = __shfl_up_sync(0xffffffffu, xs, off);
        if (lane >= off) xs += y;
    }
    if (lane == 31) wsum[wp] = xs;
    int wex = xs - tsum;
    __syncthreads();
    if (threadIdx.x == 0) {
        int run = 0;
        for (int i = 0; i < 8; i++) { int v = wsum[i]; wsum[i] = run; run += v; }
    }
    __syncthreads();
    int off0 = part[blockIdx.x] + wsum[wp] + wex;
#pragma unroll
    for (int j = 0; j < 16; j++) {
        int idx = tb + j;
        if (idx < n) ro[idx] = off0 + vals[j];
    }
    if (blockIdx.x == 0 && threadIdx.x == 0) ro[n] = part[nb];
}

__global__ void fill_kernel(const int* __restrict__ src, const int* __restrict__ dst,
                            const int* __restrict__ ro, int* __restrict__ cur,
                            int* __restrict__ csr, int E) {
    for (int i = blockIdx.x * blockDim.x + threadIdx.x; i < E;
         i += gridDim.x * blockDim.x) {
        int d = dst[i];
        int pos = ro[d] + atomicAdd(&cur[d], 1);
        csr[pos] = src[i];
    }
}

// ---------------- packed f32x2 FMA helper ----------------
__device__ __forceinline__ void fma2(unsigned long long& acc, unsigned long long w, float s) {
    unsigned long long ss;
    asm("mov.b64 %0, {%1, %1};" : "=l"(ss) : "f"(s));
    asm("fma.rn.f32x2 %0, %1, %2, %0;" : "+l"(acc) : "l"(w), "l"(ss));
}

// ---------------- fused aggregate + SAGE combine ----------------
// out = relu((sum_r mean_r@Wl_r^T + b_r + x@(sum Wr_r)^T)/NR) + x
// Warp processes 4 nodes; aggregation gathered directly from CSR.
template <int NR>
__global__ void __launch_bounds__(256, 2) combine_kernel(
    const float* __restrict__ x, float* __restrict__ out, int n,
    const float* __restrict__ s0, const int* __restrict__ ro0, const int* __restrict__ c0,
    const float* __restrict__ s1, const int* __restrict__ ro1, const int* __restrict__ c1,
    const float* __restrict__ s2, const int* __restrict__ ro2, const int* __restrict__ c2,
    const float* __restrict__ Wl, const float* __restrict__ blv,
    const float* __restrict__ Wr, int t, int r0, int r1, int r2) {
    extern __shared__ float sm[];
    float* WT    = sm;                 // NR * 4096, [k][c] transposed lin_l
    float* WrT   = WT + NR * 4096;     // 4096, transposed SUM of root weights
    float* bias  = WrT + 4096;         // 64, summed biases
    float* stage = bias + 64;          // 8 warps * 4 nodes * (NR+1) * 64

    const int rs[3] = {r0, r1, r2};
    const int tid = threadIdx.x;
    for (int r = 0; r < NR; r++) {
        const float* W = Wl + ((size_t)t * 5 + rs[r]) * 4096;
        for (int i = tid; i < 4096; i += 256) {
            int c = i >> 6, k = i & 63;
            WT[r * 4096 + k * 64 + c] = W[i];
        }
    }
    for (int i = tid; i < 4096; i += 256) {
        int c = i >> 6, k = i & 63;
        float s = 0.f;
#pragma unroll
        for (int r = 0; r < NR; r++) s += Wr[((size_t)t * 5 + rs[r]) * 4096 + i];
        WrT[k * 64 + c] = s;
    }
    if (tid < 64) {
        float s = 0.f;
#pragma unroll
        for (int r = 0; r < NR; r++) s += blv[((size_t)t * 5 + rs[r]) * 64 + tid];
        bias[tid] = s;
    }
    __syncthreads();

    const int lane = tid & 31, w = tid >> 5;
    float* st = stage + w * (4 * (NR + 1) * 64);
    const float* srcs[3] = {s0, s1, s2};
    const int* ros[3] = {ro0, ro1, ro2};
    const int* csrs[3] = {c0, c1, c2};
    const float inv = 1.0f / (float)NR;
    const int ngroups = (n + 3) >> 2;

    float2 bb = *reinterpret_cast<const float2*>(bias + 2 * lane);
    unsigned long long accb;
    asm("mov.b64 %0, {%1, %2};" : "=l"(accb) : "f"(bb.x), "f"(bb.y));

    for (int g = blockIdx.x * 8 + w; g < ngroups; g += gridDim.x * 8) {
        float2 xv[4];
#pragma unroll
        for (int m = 0; m < 4; m++) {
            int nd = g * 4 + m;
            bool act = nd < n;
            int ndc = act ? nd : 0;
#pragma unroll
            for (int r = 0; r < NR; r++) {
                int base = __ldg(&ros[r][ndc]);
                int deg = act ? (__ldg(&ros[r][ndc + 1]) - base) : 0;
                const float* S = srcs[r];
                const int* C = csrs[r] + base;
                float sx = 0.f, sy = 0.f;
                int i = 0;
                for (; i + 4 <= deg; i += 4) {
                    int n0 = __ldg(C + i), n1 = __ldg(C + i + 1);
                    int n2 = __ldg(C + i + 2), n3 = __ldg(C + i + 3);
                    float2 v0 = *reinterpret_cast<const float2*>(S + (size_t)n0 * HD + 2 * lane);
                    float2 v1 = *reinterpret_cast<const float2*>(S + (size_t)n1 * HD + 2 * lane);
                    float2 v2 = *reinterpret_cast<const float2*>(S + (size_t)n2 * HD + 2 * lane);
                    float2 v3 = *reinterpret_cast<const float2*>(S + (size_t)n3 * HD + 2 * lane);
                    sx += (v0.x + v1.x) + (v2.x + v3.x);
                    sy += (v0.y + v1.y) + (v2.y + v3.y);
                }
                for (; i < deg; i++) {
                    int nn = __ldg(C + i);
                    float2 v = *reinterpret_cast<const float2*>(S + (size_t)nn * HD + 2 * lane);
                    sx += v.x; sy += v.y;
                }
                float ic = deg > 0 ? 1.0f / (float)deg : 0.f;
                st[(m * (NR + 1) + r) * 64 + 2 * lane]     = sx * ic;
                st[(m * (NR + 1) + r) * 64 + 2 * lane + 1] = sy * ic;
            }
            float2 xx = *reinterpret_cast<const float2*>(x + (size_t)ndc * HD + 2 * lane);
            xv[m] = xx;
            st[(m * (NR + 1) + NR) * 64 + 2 * lane]     = xx.x;
            st[(m * (NR + 1) + NR) * 64 + 2 * lane + 1] = xx.y;
        }
        __syncwarp();

        unsigned long long acc0 = accb, acc1 = accb, acc2 = accb, acc3 = accb;
#pragma unroll 2
        for (int k0 = 0; k0 < 64; k0 += 4) {
#pragma unroll
            for (int mat = 0; mat < NR + 1; mat++) {
                const float* Wm = (mat < NR) ? (WT + mat * 4096) : WrT;
                float4 b0 = *reinterpret_cast<const float4*>(st + (0 * (NR + 1) + mat) * 64 + k0);
                float4 b1 = *reinterpret_cast<const float4*>(st + (1 * (NR + 1) + mat) * 64 + k0);
                float4 b2 = *reinterpret_cast<const float4*>(st + (2 * (NR + 1) + mat) * 64 + k0);
                float4 b3 = *reinterpret_cast<const float4*>(st + (3 * (NR + 1) + mat) * 64 + k0);
#pragma unroll
                for (int kk = 0; kk < 4; kk++) {
                    unsigned long long wv = *reinterpret_cast<const unsigned long long*>(
                        Wm + (k0 + kk) * 64 + 2 * lane);
                    float e0 = kk == 0 ? b0.x : kk == 1 ? b0.y : kk == 2 ? b0.z : b0.w;
                    float e1 = kk == 0 ? b1.x : kk == 1 ? b1.y : kk == 2 ? b1.z : b1.w;
                    float e2 = kk == 0 ? b2.x : kk == 1 ? b2.y : kk == 2 ? b2.z : b2.w;
                    float e3 = kk == 0 ? b3.x : kk == 1 ? b3.y : kk == 2 ? b3.z : b3.w;
                    fma2(acc0, wv, e0);
                    fma2(acc1, wv, e1);
                    fma2(acc2, wv, e2);
                    fma2(acc3, wv, e3);
                }
            }
        }
#pragma unroll
        for (int m = 0; m < 4; m++) {
            int nd = g * 4 + m;
            if (nd >= n) break;
            unsigned long long a = m == 0 ? acc0 : m == 1 ? acc1 : m == 2 ? acc2 : acc3;
            float ax, ay;
            asm("mov.b64 {%0, %1}, %2;" : "=f"(ax), "=f"(ay) : "l"(a));
            float2 res;
            res.x = fmaxf(ax * inv, 0.f) + xv[m].x;
            res.y = fmaxf(ay * inv, 0.f) + xv[m].y;
            *reinterpret_cast<float2*>(out + (size_t)nd * HD + 2 * lane) = res;
        }
        __syncwarp();
    }
}

// ---------------- column sums for global mean pooling ----------------
__global__ void colsum_kernel(const float* __restrict__ x, int n, float* __restrict__ outsum) {
    const int lane = threadIdx.x & 31;
    const int w = (blockIdx.x * blockDim.x + threadIdx.x) >> 5;
    const int nw = (gridDim.x * blockDim.x) >> 5;
    float2 acc = make_float2(0.f, 0.f);
    for (int r = w; r < n; r += nw) {
        float2 v = *reinterpret_cast<const float2*>(x + (size_t)r * HD + 2 * lane);
        acc.x += v.x; acc.y += v.y;
    }
    float* a = outsum + 2 * lane;
    asm volatile("red.global.add.v2.f32 [%0], {%1, %2};"
                 :: "l"(a), "f"(acc.x), "f"(acc.y) : "memory");
}

// ---------------- crime head (tiny) ----------------
__global__ void head_kernel(const float* __restrict__ gsum,
                            const float* __restrict__ Wc1, const float* __restrict__ bc1,
                            const float* __restrict__ Wc2, const float* __restrict__ bc2,
                            float* __restrict__ out) {
    __shared__ float g[192];
    __shared__ float h[64];
    int tid = threadIdx.x;
    if (tid < 192) {
        float nrm = tid < 64 ? (1.f / NP) : (tid < 128 ? (1.f / NO) : (1.f / NL));
        g[tid] = gsum[tid] * nrm;
    }
    __syncthreads();
    if (tid < 64) {
        float a = bc1[tid];
        for (int k = 0; k < 192; k++) a = fmaf(g[k], Wc1[tid * 192 + k], a);
        h[tid] = fmaxf(a, 0.f);
    }
    __syncthreads();
    if (tid < 20) {
        float a = bc2[tid];
        for (int k = 0; k < 64; k++) a = fmaf(h[k], Wc2[tid * 64 + k], a);
        out[tid] = a;
    }
}

// ---------------- suspect head: per-person MLP 64->32->1 ----------------
__global__ void __launch_bounds__(256) suspect_kernel(
    const float* __restrict__ p, const float* __restrict__ Ws1, const float* __restrict__ bs1,
    const float* __restrict__ Ws2, const float* __restrict__ bs2, float* __restrict__ out) {
    __shared__ float W1T[64 * 32];
    __shared__ float w2[32], b1[32];
    __shared__ float stage[8][64];
    int tid = threadIdx.x;
    for (int i = tid; i < 2048; i += 256) {
        int j = i >> 6, k = i & 63;
        W1T[k * 32 + j] = Ws1[i];
    }
    if (tid < 32) { w2[tid] = Ws2[tid]; b1[tid] = bs1[tid]; }
    __syncthreads();
    const float b2 = __ldg(bs2);
    const int lane = tid & 31, w = tid >> 5;
    const int wg = blockIdx.x * 8 + w;
    const int nw = gridDim.x * 8;
    for (int nd = wg; nd < NP; nd += nw) {
        float2 v = *reinterpret_cast<const float2*>(p + (size_t)nd * HD + 2 * lane);
        stage[w][2 * lane] = v.x; stage[w][2 * lane + 1] = v.y;
        __syncwarp();
        float acc = b1[lane];
#pragma unroll 8
        for (int k = 0; k < 64; k++)
            acc = fmaf(stage[w][k], W1T[k * 32 + lane], acc);
        float s = fmaxf(acc, 0.f) * w2[lane];
#pragma unroll
        for (int off = 16; off; off >>= 1) s += __shfl_xor_sync(0xffffffffu, s, off);
        if (lane == 0) out[20 + nd] = s + b2;
        __syncwarp();
    }
}

// ---------------- orchestration ----------------
extern "C" void kernel_launch(void* const* d_in, const int* in_sizes, int n_in,
                              void* d_out, int out_size) {
    const int* x_person   = (const int*)d_in[0];
    const int* x_object   = (const int*)d_in[1];
    const int* x_location = (const int*)d_in[2];
    const int* acts_src = (const int*)d_in[3];
    const int* acts_dst = (const int*)d_in[4];
    const int* uses_src = (const int*)d_in[5];
    const int* uses_dst = (const int*)d_in[6];
    const int* at_src   = (const int*)d_in[7];
    const int* at_dst   = (const int*)d_in[8];
    const float* person_emb   = (const float*)d_in[9];
    const float* object_emb   = (const float*)d_in[10];
    const float* location_emb = (const float*)d_in[11];
    const float* Wl  = (const float*)d_in[12];
    const float* bl  = (const float*)d_in[13];
    const float* Wr  = (const float*)d_in[14];
    const float* Wc1 = (const float*)d_in[15];
    const float* bc1 = (const float*)d_in[16];
    const float* Wc2 = (const float*)d_in[17];
    const float* bc2 = (const float*)d_in[18];
    const float* Ws1 = (const float*)d_in[19];
    const float* bs1 = (const float*)d_in[20];
    const float* Ws2 = (const float*)d_in[21];
    const float* bs2 = (const float*)d_in[22];
    float* out = (float*)d_out;

    float* nodes = nullptr; cudaGetSymbolAddress((void**)&nodes, g_nodes);
    int*   csr   = nullptr; cudaGetSymbolAddress((void**)&csr, g_csr);
    int*   rowoff= nullptr; cudaGetSymbolAddress((void**)&rowoff, g_rowoff);
    int*   cnt   = nullptr; cudaGetSymbolAddress((void**)&cnt, g_cnt);
    int*   part  = nullptr; cudaGetSymbolAddress((void**)&part, g_part);
    float* sums  = nullptr; cudaGetSymbolAddress((void**)&sums, g_sums);

    const size_t NODESZ = (size_t)(NP + NO + NL) * HD;
    float* bufA = nodes;
    float* bufB = nodes + NODESZ;

    int* csr0 = csr;               // person <- acts (src persons)
    int* csr1 = csr + NE;          // person <- rev_uses (src objects)
    int* csr2 = csr + 2 * NE;      // person <- rev_at (src locations)
    int* csr3 = csr + 3 * NE;      // object <- uses (src persons)
    int* csr4 = csr + 4 * NE;      // location <- at (src persons)

    int* ro_p1 = rowoff;
    int* ro_p2 = rowoff + (NP + 1);
    int* ro_p3 = rowoff + 2 * (NP + 1);
    int* ro_o  = rowoff + 3 * (NP + 1);
    int* ro_l  = ro_o + (NO + 1);

    int* cntp1 = cnt;
    int* cntp2 = cnt + NP;
    int* cntp3 = cnt + 2 * NP;
    int* cnto  = cnt + 3 * NP;
    int* cntl  = cnt + 3 * NP + NO;

    const int SM3 = (3 * 4096 + 4096 + 64 + 8 * 4 * 4 * 64) * 4;  // 98560 B
    const int SM1 = (1 * 4096 + 4096 + 64 + 8 * 4 * 2 * 64) * 4;  // 49408 B
    cudaFuncSetAttribute(combine_kernel<3>, cudaFuncAttributeMaxDynamicSharedMemorySize, SM3);
    cudaFuncSetAttribute(combine_kernel<1>, cudaFuncAttributeMaxDynamicSharedMemorySize, SM1);

    // Phase A: embedding gathers
    gather_kernel<<<2048, 256>>>(x_person, person_emb, bufA, NP);
    gather_kernel<<<1024, 256>>>(x_object, object_emb, bufA + (size_t)NP * HD, NO);
    gather_kernel<<<512, 256>>>(x_location, location_emb, bufA + (size_t)(NP + NO) * HD, NL);

    // Phase B: CSR build (counts -> scan -> fill)
    zero_kernel<<<512, 256>>>((float*)cnt, (size_t)(3 * NP + NO + NL));
    count_kernel<<<1024, 256>>>(acts_dst, cntp1, NE);
    count_kernel<<<1024, 256>>>(uses_src, cntp2, NE);
    count_kernel<<<1024, 256>>>(at_src,   cntp3, NE);
    count_kernel<<<1024, 256>>>(uses_dst, cnto,  NE);
    count_kernel<<<1024, 256>>>(at_dst,   cntl,  NE);

    const int NBP = (NP + SCHUNK - 1) / SCHUNK;  // 49
    const int NBO = (NO + SCHUNK - 1) / SCHUNK;  // 25
    const int NBL = (NL + SCHUNK - 1) / SCHUNK;  // 13
    scan_reduce<<<NBP, 256>>>(cntp1, part + 0 * 64, NP);
    scan_reduce<<<NBP, 256>>>(cntp2, part + 1 * 64, NP);
    scan_reduce<<<NBP, 256>>>(cntp3, part + 2 * 64, NP);
    scan_reduce<<<NBO, 256>>>(cnto,  part + 3 * 64, NO);
    scan_reduce<<<NBL, 256>>>(cntl,  part + 4 * 64, NL);
    scan_part<<<1, 32>>>(part + 0 * 64, NBP);
    scan_part<<<1, 32>>>(part + 1 * 64, NBP);
    scan_part<<<1, 32>>>(part + 2 * 64, NBP);
    scan_part<<<1, 32>>>(part + 3 * 64, NBO);
    scan_part<<<1, 32>>>(part + 4 * 64, NBL);
    scan_write<<<NBP, 256>>>(cntp1, part + 0 * 64, ro_p1, NP, NBP);
    scan_write<<<NBP, 256>>>(cntp2, part + 1 * 64, ro_p2, NP, NBP);
    scan_write<<<NBP, 256>>>(cntp3, part + 2 * 64, ro_p3, NP, NBP);
    scan_write<<<NBO, 256>>>(cnto,  part + 3 * 64, ro_o,  NO, NBO);
    scan_write<<<NBL, 256>>>(cntl,  part + 4 * 64, ro_l,  NL, NBL);

    zero_kernel<<<512, 256>>>((float*)cnt, (size_t)(3 * NP + NO + NL));  // cursors
    fill_kernel<<<1024, 256>>>(acts_src, acts_dst, ro_p1, cntp1, csr0, NE);
    fill_kernel<<<1024, 256>>>(uses_dst, uses_src, ro_p2, cntp2, csr1, NE);
    fill_kernel<<<1024, 256>>>(at_dst,   at_src,   ro_p3, cntp3, csr2, NE);
    fill_kernel<<<1024, 256>>>(uses_src, uses_dst, ro_o,  cnto,  csr3, NE);
    fill_kernel<<<1024, 256>>>(at_src,   at_dst,   ro_l,  cntl,  csr4, NE);

    // Phase C: 3 GNN layers (fused aggregate + combine)
    float* pc = bufA;
    float* pn = bufB;
    for (int t = 0; t < 3; t++) {
        float* p = pc;
        float* o = pc + (size_t)NP * HD;
        float* l = pc + (size_t)(NP + NO) * HD;
        combine_kernel<3><<<296, 256, SM3>>>(p, pn, NP,
            p, ro_p1, csr0, o, ro_p2, csr1, l, ro_p3, csr2,
            Wl, bl, Wr, t, 0, 2, 4);
        combine_kernel<1><<<592, 256, SM1>>>(o, pn + (size_t)NP * HD, NO,
            p, ro_o, csr3, p, ro_o, csr3, p, ro_o, csr3,
            Wl, bl, Wr, t, 1, 0, 0);
        combine_kernel<1><<<296, 256, SM1>>>(l, pn + (size_t)(NP + NO) * HD, NL,
            p, ro_l, csr4, p, ro_l, csr4, p, ro_l, csr4,
            Wl, bl, Wr, t, 3, 0, 0);
        float* tmp = pc; pc = pn; pn = tmp;
    }

    // Phase D: heads
    float* p = pc;
    float* o = pc + (size_t)NP * HD;
    float* l = pc + (size_t)(NP + NO) * HD;
    zero_kernel<<<1, 64>>>(sums, 192);
    colsum_kernel<<<1024, 256>>>(p, NP, sums);
    colsum_kernel<<<512, 256>>>(o, NO, sums + 64);
    colsum_kernel<<<256, 256>>>(l, NL, sums + 128);
    head_kernel<<<1, 256>>>(sums, Wc1, bc1, Wc2, bc2, out);
    suspect_kernel<<<2048, 256>>>(p, Ws1, bs1, Ws2, bs2, out);
}

// round 6
// speedup vs baseline: 1.3919x; 1.0987x over previous
#include <cuda_runtime.h>
#include <cstdint>

#define NP 200000
#define NO 100000
#define NL 50000
#define NE 1000000
#define HD 64

#define GP 50000   // person groups (4 nodes each)
#define GO 25000
#define GL 12500
#define NCNT (3 * NP + NO + NL)   // 750000

// ---------------- device scratch (static, allowed) ----------------
__device__ float g_nodes[2][(size_t)(NP + NO + NL) * HD];   // double-buffered features
__device__ int   g_csr[5 * NE];                             // single global CSR
__device__ int   g_rowoff[NCNT + 8];                        // global exclusive scan
__device__ int   g_cnt[NCNT];                               // counts, then cursors
__device__ int   g_part[256];                               // scan partials
__device__ float g_sums[3 * HD];                            // column sums

// ---------------- utility kernels ----------------
__global__ void zero_kernel(float* __restrict__ p, size_t n) {
    size_t n4 = n >> 2;
    float4 z = make_float4(0.f, 0.f, 0.f, 0.f);
    for (size_t i = (size_t)blockIdx.x * blockDim.x + threadIdx.x; i < n4;
         i += (size_t)gridDim.x * blockDim.x)
        reinterpret_cast<float4*>(p)[i] = z;
}

__global__ void gather_all(const int* __restrict__ xp, const int* __restrict__ xo,
                           const int* __restrict__ xl,
                           const float* __restrict__ pe, const float* __restrict__ oe,
                           const float* __restrict__ le, float* __restrict__ out) {
    int i = blockIdx.x * blockDim.x + threadIdx.x;
    int total = (NP + NO + NL) * 16;
    if (i >= total) return;
    int node = i >> 4, c = i & 15;
    const int* idx;
    const float* emb;
    int local;
    if (node < NP) { idx = xp; emb = pe; local = node; }
    else if (node < NP + NO) { idx = xo; emb = oe; local = node - NP; }
    else { idx = xl; emb = le; local = node - NP - NO; }
    int e = __ldg(&idx[local]);
    reinterpret_cast<float4*>(out)[(size_t)node * 16 + c] =
        reinterpret_cast<const float4*>(emb)[(size_t)e * 16 + c];
}

// ---------------- CSR build: one pass over all 5 relations ----------------
__global__ void count_all(const int* __restrict__ acts_dst, const int* __restrict__ uses_src,
                          const int* __restrict__ at_src, const int* __restrict__ uses_dst,
                          const int* __restrict__ at_dst, int* __restrict__ cnt) {
    int i = blockIdx.x * blockDim.x + threadIdx.x;
    if (i >= 5 * NE) return;
    int rel = i / NE, e = i - rel * NE;
    int d, off;
    switch (rel) {
        case 0: d = __ldg(&acts_dst[e]); off = 0;           break;
        case 1: d = __ldg(&uses_src[e]); off = NP;          break;
        case 2: d = __ldg(&at_src[e]);   off = 2 * NP;      break;
        case 3: d = __ldg(&uses_dst[e]); off = 3 * NP;      break;
        default: d = __ldg(&at_dst[e]);  off = 3 * NP + NO; break;
    }
    atomicAdd(&cnt[off + d], 1);
}

#define SCHUNK 4096
__global__ void scan_reduce(const int* __restrict__ in, int* __restrict__ part, int n) {
    __shared__ int s[256];
    int base = blockIdx.x * SCHUNK;
    int acc = 0;
    for (int i = threadIdx.x; i < SCHUNK; i += 256) {
        int idx = base + i;
        if (idx < n) acc += in[idx];
    }
    s[threadIdx.x] = acc;
    __syncthreads();
    for (int off = 128; off; off >>= 1) {
        if (threadIdx.x < off) s[threadIdx.x] += s[threadIdx.x + off];
        __syncthreads();
    }
    if (threadIdx.x == 0) part[blockIdx.x] = s[0];
}

// block-parallel exclusive scan of <=256 partials
__global__ void scan_part(int* part, int nb) {
    int tid = threadIdx.x;
    int v = tid < nb ? part[tid] : 0;
    int lane = tid & 31, wp = tid >> 5;
    int x = v;
#pragma unroll
    for (int off = 1; off < 32; off <<= 1) {
        int y = __shfl_up_sync(0xffffffffu, x, off);
        if (lane >= off) x += y;
    }
    __shared__ int ws[8];
    if (lane == 31) ws[wp] = x;
    __syncthreads();
    if (tid == 0) {
        int run = 0;
        for (int i = 0; i < 8; i++) { int t = ws[i]; ws[i] = run; run += t; }
    }
    __syncthreads();
    int incl = x + ws[wp];
    if (tid < nb) part[tid] = incl - v;
    if (tid == nb - 1) part[nb] = incl;
}

__global__ void scan_write(const int* __restrict__ in, const int* __restrict__ part,
                           int* __restrict__ ro, int n, int nb) {
    __shared__ int wsum[8];
    int base = blockIdx.x * SCHUNK;
    int vals[16];
    int tsum = 0;
    int tb = base + threadIdx.x * 16;
#pragma unroll
    for (int j = 0; j < 16; j++) {
        int idx = tb + j;
        int v = (idx < n) ? in[idx] : 0;
        vals[j] = tsum;
        tsum += v;
    }
    int lane = threadIdx.x & 31, wp = threadIdx.x >> 5;
    int xs = tsum;
#pragma unroll
    for (int off = 1; off < 32; off <<= 1) {
        int y = __shfl_up_sync(0xffffffffu, xs, off);
        if (lane >= off) xs += y;
    }
    if (lane == 31) wsum[wp] = xs;
    int wex = xs - tsum;
    __syncthreads();
    if (threadIdx.x == 0) {
        int run = 0;
        for (int i = 0; i < 8; i++) { int v = wsum[i]; wsum[i] = run; run += v; }
    }
    __syncthreads();
    int off0 = part[blockIdx.x] + wsum[wp] + wex;
#pragma unroll
    for (int j = 0; j < 16; j++) {
        int idx = tb + j;
        if (idx < n) ro[idx] = off0 + vals[j];
    }
    if (blockIdx.x == 0 && threadIdx.x == 0) ro[n] = part[nb];
}

__global__ void copy_int(const int* __restrict__ src, int* __restrict__ dst, int n4) {
    int i = blockIdx.x * blockDim.x + threadIdx.x;
    if (i < n4) reinterpret_cast<int4*>(dst)[i] = reinterpret_cast<const int4*>(src)[i];
}

__global__ void fill_all(const int* __restrict__ acts_src, const int* __restrict__ acts_dst,
                         const int* __restrict__ uses_src, const int* __restrict__ uses_dst,
                         const int* __restrict__ at_src, const int* __restrict__ at_dst,
                         int* __restrict__ cur, int* __restrict__ csr) {
    int i = blockIdx.x * blockDim.x + threadIdx.x;
    if (i >= 5 * NE) return;
    int rel = i / NE, e = i - rel * NE;
    int d, s, off;
    switch (rel) {
        case 0: d = __ldg(&acts_dst[e]); s = __ldg(&acts_src[e]); off = 0;           break;
        case 1: d = __ldg(&uses_src[e]); s = __ldg(&uses_dst[e]); off = NP;          break;
        case 2: d = __ldg(&at_src[e]);   s = __ldg(&at_dst[e]);   off = 2 * NP;      break;
        case 3: d = __ldg(&uses_dst[e]); s = __ldg(&uses_src[e]); off = 3 * NP;      break;
        default: d = __ldg(&at_dst[e]);  s = __ldg(&at_src[e]);   off = 3 * NP + NO; break;
    }
    int pos = atomicAdd(&cur[off + d], 1);
    csr[pos] = s;
}

// ---------------- packed f32x2 FMA helper ----------------
__device__ __forceinline__ void fma2(unsigned long long& acc, unsigned long long w, float s) {
    unsigned long long ss;
    asm("mov.b64 %0, {%1, %1};" : "=l"(ss) : "f"(s));
    asm("fma.rn.f32x2 %0, %1, %2, %0;" : "+l"(acc) : "l"(w), "l"(ss));
}

// ---------------- unified fused aggregate + SAGE combine ----------------
#define WSTRIDE 66                    // padded row stride (floats) -> no STS bank conflicts
#define WMAT (64 * WSTRIDE)           // 4224 floats per matrix

template <int NR, int MA, int MB, int MC, int MD>
__device__ __forceinline__ void do_group(
    int nd0, int n, const float* __restrict__ x, float* __restrict__ out,
    const float* s0, const float* s1, const float* s2,
    const int* ro0, const int* ro1, const int* ro2,
    const int* __restrict__ csr,
    const float* __restrict__ WT, const float* __restrict__ bias,
    float* __restrict__ st, int lane, float inv) {
    constexpr int mats[4] = {MA, MB, MC, MD};
    const float* srcs[3] = {s0, s1, s2};
    const int* ros[3] = {ro0, ro1, ro2};
    float2 xv[4];
#pragma unroll
    for (int m = 0; m < 4; m++) {
        int nd = nd0 + m;
        bool act = nd < n;
        int ndc = act ? nd : 0;
#pragma unroll
        for (int r = 0; r < NR; r++) {
            int base = __ldg(&ros[r][ndc]);
            int deg = act ? (__ldg(&ros[r][ndc + 1]) - base) : 0;
            const float* S = srcs[r];
            const int* C = csr + base;
            float sx = 0.f, sy = 0.f;
            int i = 0;
            for (; i + 4 <= deg; i += 4) {
                int n0 = __ldg(C + i), n1 = __ldg(C + i + 1);
                int n2 = __ldg(C + i + 2), n3 = __ldg(C + i + 3);
                float2 v0 = *reinterpret_cast<const float2*>(S + (size_t)n0 * HD + 2 * lane);
                float2 v1 = *reinterpret_cast<const float2*>(S + (size_t)n1 * HD + 2 * lane);
                float2 v2 = *reinterpret_cast<const float2*>(S + (size_t)n2 * HD + 2 * lane);
                float2 v3 = *reinterpret_cast<const float2*>(S + (size_t)n3 * HD + 2 * lane);
                sx += (v0.x + v1.x) + (v2.x + v3.x);
                sy += (v0.y + v1.y) + (v2.y + v3.y);
            }
            for (; i < deg; i++) {
                int nn = __ldg(C + i);
                float2 v = *reinterpret_cast<const float2*>(S + (size_t)nn * HD + 2 * lane);
                sx += v.x; sy += v.y;
            }
            float ic = deg > 0 ? 1.0f / (float)deg : 0.f;
            st[(m * (NR + 1) + r) * 64 + 2 * lane]     = sx * ic;
            st[(m * (NR + 1) + r) * 64 + 2 * lane + 1] = sy * ic;
        }
        float2 xx = *reinterpret_cast<const float2*>(x + (size_t)ndc * HD + 2 * lane);
        xv[m] = xx;
        st[(m * (NR + 1) + NR) * 64 + 2 * lane]     = xx.x;
        st[(m * (NR + 1) + NR) * 64 + 2 * lane + 1] = xx.y;
    }
    __syncwarp();

    float2 bb = *reinterpret_cast<const float2*>(bias + 2 * lane);
    unsigned long long accb;
    asm("mov.b64 %0, {%1, %2};" : "=l"(accb) : "f"(bb.x), "f"(bb.y));
    unsigned long long acc0 = accb, acc1 = accb, acc2 = accb, acc3 = accb;
#pragma unroll 2
    for (int k0 = 0; k0 < 64; k0 += 4) {
#pragma unroll
        for (int mi = 0; mi < NR + 1; mi++) {
            const float* Wm = WT + mats[mi] * WMAT;
            float4 b0 = *reinterpret_cast<const float4*>(st + (0 * (NR + 1) + mi) * 64 + k0);
            float4 b1 = *reinterpret_cast<const float4*>(st + (1 * (NR + 1) + mi) * 64 + k0);
            float4 b2 = *reinterpret_cast<const float4*>(st + (2 * (NR + 1) + mi) * 64 + k0);
            float4 b3 = *reinterpret_cast<const float4*>(st + (3 * (NR + 1) + mi) * 64 + k0);
#pragma unroll
            for (int kk = 0; kk < 4; kk++) {
                unsigned long long wv = *reinterpret_cast<const unsigned long long*>(
                    Wm + (k0 + kk) * WSTRIDE + 2 * lane);
                float e0 = kk == 0 ? b0.x : kk == 1 ? b0.y : kk == 2 ? b0.z : b0.w;
                float e1 = kk == 0 ? b1.x : kk == 1 ? b1.y : kk == 2 ? b1.z : b1.w;
                float e2 = kk == 0 ? b2.x : kk == 1 ? b2.y : kk == 2 ? b2.z : b2.w;
                float e3 = kk == 0 ? b3.x : kk == 1 ? b3.y : kk == 2 ? b3.z : b3.w;
                fma2(acc0, wv, e0);
                fma2(acc1, wv, e1);
                fma2(acc2, wv, e2);
                fma2(acc3, wv, e3);
            }
        }
    }
#pragma unroll
    for (int m = 0; m < 4; m++) {
        int nd = nd0 + m;
        if (nd >= n) break;
        unsigned long long a = m == 0 ? acc0 : m == 1 ? acc1 : m == 2 ? acc2 : acc3;
        float ax, ay;
        asm("mov.b64 {%0, %1}, %2;" : "=f"(ax), "=f"(ay) : "l"(a));
        float2 res;
        res.x = fmaxf(ax * inv, 0.f) + xv[m].x;
        res.y = fmaxf(ay * inv, 0.f) + xv[m].y;
        *reinterpret_cast<float2*>(out + (size_t)nd * HD + 2 * lane) = res;
    }
    __syncwarp();
}

// smem: 8 mats * WMAT + 192 bias + 16 warps * 1024 stage
#define SMEMC ((8 * WMAT + 192 + 16 * 1024) * 4)

__global__ void __launch_bounds__(512, 1) combine_all(
    const float* __restrict__ xin, float* __restrict__ xout,
    const int* __restrict__ rowoff, const int* __restrict__ csr,
    const float* __restrict__ Wl, const float* __restrict__ blv,
    const float* __restrict__ Wr, int t) {
    extern __shared__ float sm[];
    float* WT   = sm;                   // 8 mats, stride-padded, transposed [k][c]
    float* bias = WT + 8 * WMAT;        // 3 * 64
    float* stage = bias + 192;          // 16 warps * 4 nodes * 4 slots * 64

    const int tid = threadIdx.x;
    const float* WlB = Wl + (size_t)t * 5 * 4096;
    const float* WrB = Wr + (size_t)t * 5 * 4096;
    // mats 0..4 = Wl[t][0..4]^T
    for (int i = tid; i < 5 * 4096; i += 512) {
        int m = i >> 12, j = i & 4095;
        int c = j >> 6, k = j & 63;
        WT[m * WMAT + k * WSTRIDE + c] = WlB[i];
    }
    // mat 5 = (Wr0+Wr2+Wr4)^T, mat 6 = Wr1^T, mat 7 = Wr3^T
    for (int i = tid; i < 4096; i += 512) {
        int c = i >> 6, k = i & 63;
        WT[5 * WMAT + k * WSTRIDE + c] = WrB[i] + WrB[2 * 4096 + i] + WrB[4 * 4096 + i];
        WT[6 * WMAT + k * WSTRIDE + c] = WrB[4096 + i];
        WT[7 * WMAT + k * WSTRIDE + c] = WrB[3 * 4096 + i];
    }
    if (tid < 64) {
        const float* b = blv + (size_t)t * 5 * 64;
        bias[tid]       = b[tid] + b[128 + tid] + b[256 + tid];
        bias[64 + tid]  = b[64 + tid];
        bias[128 + tid] = b[192 + tid];
    }
    __syncthreads();

    const int lane = tid & 31, w = tid >> 5;
    float* st = stage + w * 1024;
    const float* P  = xin;
    const float* O  = xin + (size_t)NP * HD;
    const float* Lc = xin + (size_t)(NP + NO) * HD;

    for (int g = blockIdx.x * 16 + w; g < GP + GO + GL; g += gridDim.x * 16) {
        if (g < GP) {
            do_group<3, 0, 2, 4, 5>(g * 4, NP, P, xout,
                P, O, Lc, rowoff, rowoff + NP, rowoff + 2 * NP, csr,
                WT, bias, st, lane, 1.0f / 3.0f);
        } else if (g < GP + GO) {
            do_group<1, 1, 6, 0, 0>((g - GP) * 4, NO, O, xout + (size_t)NP * HD,
                P, P, P, rowoff + 3 * NP, rowoff + 3 * NP, rowoff + 3 * NP, csr,
                WT, bias + 64, st, lane, 1.0f);
        } else {
            do_group<1, 3, 7, 0, 0>((g - GP - GO) * 4, NL, Lc, xout + (size_t)(NP + NO) * HD,
                P, P, P, rowoff + 3 * NP + NO, rowoff + 3 * NP + NO, rowoff + 3 * NP + NO, csr,
                WT, bias + 128, st, lane, 1.0f);
        }
    }
}

// ---------------- column sums over all node types in one pass ----------------
__global__ void colsum_all(const float* __restrict__ x, float* __restrict__ sums) {
    const int lane = threadIdx.x & 31;
    const int w = (blockIdx.x * blockDim.x + threadIdx.x) >> 5;
    const int nw = (gridDim.x * blockDim.x) >> 5;
    float2 a0 = make_float2(0.f, 0.f), a1 = a0, a2 = a0;
    for (int r = w; r < NP + NO + NL; r += nw) {
        float2 v = *reinterpret_cast<const float2*>(x + (size_t)r * HD + 2 * lane);
        if (r < NP)          { a0.x += v.x; a0.y += v.y; }
        else if (r < NP + NO){ a1.x += v.x; a1.y += v.y; }
        else                 { a2.x += v.x; a2.y += v.y; }
    }
    asm volatile("red.global.add.v2.f32 [%0], {%1, %2};"
                 :: "l"(sums + 2 * lane), "f"(a0.x), "f"(a0.y) : "memory");
    asm volatile("red.global.add.v2.f32 [%0], {%1, %2};"
                 :: "l"(sums + 64 + 2 * lane), "f"(a1.x), "f"(a1.y) : "memory");
    asm volatile("red.global.add.v2.f32 [%0], {%1, %2};"
                 :: "l"(sums + 128 + 2 * lane), "f"(a2.x), "f"(a2.y) : "memory");
}

// ---------------- crime head (tiny) ----------------
__global__ void head_kernel(const float* __restrict__ gsum,
                            const float* __restrict__ Wc1, const float* __restrict__ bc1,
                            const float* __restrict__ Wc2, const float* __restrict__ bc2,
                            float* __restrict__ out) {
    __shared__ float g[192];
    __shared__ float h[64];
    int tid = threadIdx.x;
    if (tid < 192) {
        float nrm = tid < 64 ? (1.f / NP) : (tid < 128 ? (1.f / NO) : (1.f / NL));
        g[tid] = gsum[tid] * nrm;
    }
    __syncthreads();
    if (tid < 64) {
        float a = bc1[tid];
        for (int k = 0; k < 192; k++) a = fmaf(g[k], Wc1[tid * 192 + k], a);
        h[tid] = fmaxf(a, 0.f);
    }
    __syncthreads();
    if (tid < 20) {
        float a = bc2[tid];
        for (int k = 0; k < 64; k++) a = fmaf(h[k], Wc2[tid * 64 + k], a);
        out[tid] = a;
    }
}

// ---------------- suspect head: per-person MLP 64->32->1 ----------------
__global__ void __launch_bounds__(256) suspect_kernel(
    const float* __restrict__ p, const float* __restrict__ Ws1, const float* __restrict__ bs1,
    const float* __restrict__ Ws2, const float* __restrict__ bs2, float* __restrict__ out) {
    __shared__ float W1T[64 * 32];
    __shared__ float w2[32], b1[32];
    __shared__ float stage[8][64];
    int tid = threadIdx.x;
    for (int i = tid; i < 2048; i += 256) {
        int j = i >> 6, k = i & 63;
        W1T[k * 32 + j] = Ws1[i];
    }
    if (tid < 32) { w2[tid] = Ws2[tid]; b1[tid] = bs1[tid]; }
    __syncthreads();
    const float b2 = __ldg(bs2);
    const int lane = tid & 31, w = tid >> 5;
    const int wg = blockIdx.x * 8 + w;
    const int nw = gridDim.x * 8;
    for (int nd = wg; nd < NP; nd += nw) {
        float2 v = *reinterpret_cast<const float2*>(p + (size_t)nd * HD + 2 * lane);
        stage[w][2 * lane] = v.x; stage[w][2 * lane + 1] = v.y;
        __syncwarp();
        float acc = b1[lane];
#pragma unroll 8
        for (int k = 0; k < 64; k++)
            acc = fmaf(stage[w][k], W1T[k * 32 + lane], acc);
        float s = fmaxf(acc, 0.f) * w2[lane];
#pragma unroll
        for (int off = 16; off; off >>= 1) s += __shfl_xor_sync(0xffffffffu, s, off);
        if (lane == 0) out[20 + nd] = s + b2;
        __syncwarp();
    }
}

// ---------------- orchestration ----------------
extern "C" void kernel_launch(void* const* d_in, const int* in_sizes, int n_in,
                              void* d_out, int out_size) {
    const int* x_person   = (const int*)d_in[0];
    const int* x_object   = (const int*)d_in[1];
    const int* x_location = (const int*)d_in[2];
    const int* acts_src = (const int*)d_in[3];
    const int* acts_dst = (const int*)d_in[4];
    const int* uses_src = (const int*)d_in[5];
    const int* uses_dst = (const int*)d_in[6];
    const int* at_src   = (const int*)d_in[7];
    const int* at_dst   = (const int*)d_in[8];
    const float* person_emb   = (const float*)d_in[9];
    const float* object_emb   = (const float*)d_in[10];
    const float* location_emb = (const float*)d_in[11];
    const float* Wl  = (const float*)d_in[12];
    const float* bl  = (const float*)d_in[13];
    const float* Wr  = (const float*)d_in[14];
    const float* Wc1 = (const float*)d_in[15];
    const float* bc1 = (const float*)d_in[16];
    const float* Wc2 = (const float*)d_in[17];
    const float* bc2 = (const float*)d_in[18];
    const float* Ws1 = (const float*)d_in[19];
    const float* bs1 = (const float*)d_in[20];
    const float* Ws2 = (const float*)d_in[21];
    const float* bs2 = (const float*)d_in[22];
    float* out = (float*)d_out;

    float* nodes  = nullptr; cudaGetSymbolAddress((void**)&nodes, g_nodes);
    int*   csr    = nullptr; cudaGetSymbolAddress((void**)&csr, g_csr);
    int*   rowoff = nullptr; cudaGetSymbolAddress((void**)&rowoff, g_rowoff);
    int*   cnt    = nullptr; cudaGetSymbolAddress((void**)&cnt, g_cnt);
    int*   part   = nullptr; cudaGetSymbolAddress((void**)&part, g_part);
    float* sums   = nullptr; cudaGetSymbolAddress((void**)&sums, g_sums);

    int nsm = 148;
    cudaDeviceGetAttribute(&nsm, cudaDevAttrMultiProcessorCount, 0);

    const size_t NODESZ = (size_t)(NP + NO + NL) * HD;
    float* bufA = nodes;
    float* bufB = nodes + NODESZ;

    cudaFuncSetAttribute(combine_all, cudaFuncAttributeMaxDynamicSharedMemorySize, SMEMC);

    // Phase A: embedding gathers (all node types, one launch)
    gather_all<<<((NP + NO + NL) * 16 + 255) / 256, 256>>>(
        x_person, x_object, x_location, person_emb, object_emb, location_emb, bufA);

    // Phase B: global CSR build
    zero_kernel<<<256, 256>>>((float*)cnt, (size_t)NCNT);
    count_all<<<(5 * NE + 255) / 256, 256>>>(acts_dst, uses_src, at_src, uses_dst, at_dst, cnt);
    const int NB = (NCNT + SCHUNK - 1) / SCHUNK;   // 184
    scan_reduce<<<NB, 256>>>(cnt, part, NCNT);
    scan_part<<<1, 256>>>(part, NB);
    scan_write<<<NB, 256>>>(cnt, part, rowoff, NCNT, NB);
    copy_int<<<(NCNT / 4 + 255) / 256, 256>>>(rowoff, cnt, NCNT / 4);   // cursors = rowoff
    fill_all<<<(5 * NE + 255) / 256, 256>>>(acts_src, acts_dst, uses_src, uses_dst,
                                            at_src, at_dst, cnt, csr);

    // Phase C: 3 GNN layers, one unified persistent launch per layer
    float* pc = bufA;
    float* pn = bufB;
    for (int t = 0; t < 3; t++) {
        combine_all<<<nsm, 512, SMEMC>>>(pc, pn, rowoff, csr, Wl, bl, Wr, t);
        float* tmp = pc; pc = pn; pn = tmp;
    }

    // Phase D: heads
    float* p = pc;
    zero_kernel<<<1, 48>>>(sums, 192);
    colsum_all<<<512, 256>>>(p, sums);
    head_kernel<<<1, 256>>>(sums, Wc1, bc1, Wc2, bc2, out);
    suspect_kernel<<<2048, 256>>>(p, Ws1, bs1, Ws2, bs2, out);
}